// round 13
// baseline (speedup 1.0000x reference)
#include <cuda_runtime.h>
#include <cuda_bf16.h>
#include <cstdint>

#define NNODES 50000
#define NEDGES 1600000
#define MAXF   512

// ---------------- device scratch (static, no allocation) ----------------
__device__ int   g_flag;
__device__ int   g_deg[NNODES];
__device__ float g_dinv[NNODES];
__device__ float g_diag[NNODES];
__device__ int   g_rowptr[NNODES + 1];
__device__ int   g_cursor[NNODES];
__device__ int   g_ecol[NEDGES];
__device__ float g_ew[NEDGES];
__device__ float g_T1r[(size_t)NNODES * MAXF];
__device__ float g_T2r[(size_t)NNODES * MAXF];
__device__ float g_acc[(size_t)NNODES * 1000];
__device__ float g_h1 [(size_t)NNODES * 250];
__device__ float g_h1r[(size_t)NNODES * 250];
__device__ float g_h2 [(size_t)NNODES * 500];
__device__ float g_h2r[(size_t)NNODES * 500];
__device__ float g_xr [(size_t)NNODES * 512];
__device__ float g_W1r[3 * 512 * 250];
__device__ float g_W2r[3 * 250 * 500];
__device__ float g_W3r[3 * 500 * 1000];
// bf16 gather copies
__device__ __nv_bfloat16 g_xb [(size_t)NNODES * 512];
__device__ __nv_bfloat16 g_T1b[(size_t)NNODES * MAXF];
__device__ __nv_bfloat16 g_h1b[(size_t)NNODES * 250];
__device__ __nv_bfloat16 g_h2b[(size_t)NNODES * 500];

__device__ __forceinline__ float to_tf32(float x) {
    float y;
    asm("cvt.rna.tf32.f32 %0, %1;" : "=f"(y) : "f"(x));
    return y;
}

// ---------------- index width detection (parallel) ----------------
__global__ void k_detect(const int* e32) {
    __shared__ int ok;
    if (threadIdx.x == 0) ok = 1;
    __syncthreads();
    if (e32[2 * threadIdx.x + 1] != 0) ok = 0;   // benign race: only writes 0
    __syncthreads();
    if (threadIdx.x == 0) g_flag = ok;
}

__device__ __forceinline__ int load_idx(const void* e, long long i) {
    if (g_flag) return (int)((const long long*)e)[i];
    return ((const int*)e)[i];
}

// ---------------- graph setup ----------------
__global__ void k_init() {
    int i = blockIdx.x * blockDim.x + threadIdx.x;
    if (i < NNODES) { g_deg[i] = 0; g_cursor[i] = 0; }
}

__global__ void k_degree(const void* e) {
    int i = blockIdx.x * blockDim.x + threadIdx.x;
    if (i < NEDGES) {
        int dst = load_idx(e, (long long)NEDGES + i);
        atomicAdd(&g_deg[dst], 1);
    }
}

__global__ void k_node() {
    int i = blockIdx.x * blockDim.x + threadIdx.x;
    if (i < NNODES) {
        int d = g_deg[i];
        g_dinv[i] = d > 0 ? rsqrtf((float)d) : 0.0f;
        g_diag[i] = d > 0 ? 0.0f : -1.0f;
    }
}

__global__ void k_scan() {
    __shared__ int warp_sums[32];
    int tid  = threadIdx.x;
    int lane = tid & 31;
    int wid  = tid >> 5;
    int carry = 0;
    for (int base = 0; base < NNODES; base += 1024) {
        int i = base + tid;
        int v = (i < NNODES) ? g_deg[i] : 0;
        int x = v;
        #pragma unroll
        for (int o = 1; o < 32; o <<= 1) {
            int y = __shfl_up_sync(0xffffffffu, x, o);
            if (lane >= o) x += y;
        }
        if (lane == 31) warp_sums[wid] = x;
        __syncthreads();
        if (tid < 32) {
            int s = warp_sums[tid];
            #pragma unroll
            for (int o = 1; o < 32; o <<= 1) {
                int y = __shfl_up_sync(0xffffffffu, s, o);
                if (tid >= o) s += y;
            }
            warp_sums[tid] = s;
        }
        __syncthreads();
        int incl = x + (wid > 0 ? warp_sums[wid - 1] : 0);
        if (i < NNODES) g_rowptr[i] = carry + incl - v;
        int total = warp_sums[31];
        __syncthreads();
        carry += total;
    }
    if (tid == 0) g_rowptr[NNODES] = carry;
}

__global__ void k_scatter(const void* e) {
    int i = blockIdx.x * blockDim.x + threadIdx.x;
    if (i < NEDGES) {
        int src = load_idx(e, i);
        int dst = load_idx(e, (long long)NEDGES + i);
        float w = -g_dinv[dst] * g_dinv[src];
        int pos = g_rowptr[dst] + atomicAdd(&g_cursor[dst], 1);
        g_ecol[pos] = src;
        g_ew[pos]   = w;
    }
}

// ---------------- rounding helpers ----------------
__global__ void k_round(const float* __restrict__ in, float* __restrict__ dst, int n) {
    int i = blockIdx.x * blockDim.x + threadIdx.x;
    if (i < n) dst[i] = to_tf32(in[i]);
}

__global__ void k_round_dual(const float* __restrict__ in, float* __restrict__ r,
                             __nv_bfloat16* __restrict__ b, int n) {
    int i = blockIdx.x * blockDim.x + threadIdx.x;
    if (i < n) {
        float v = in[i];
        r[i] = to_tf32(v);
        b[i] = __float2bfloat16(v);
    }
}

// ---------------- SpMM bodies (bf16 gather, fp32 accumulate) ----------------
__device__ __forceinline__ void spmm_b4_body(
    int node, int f, const uint2* __restrict__ hb, const float4* __restrict__ hs,
    const float4* __restrict__ t0, float4* __restrict__ out_r,
    uint2* __restrict__ out_b, int F4, int mode)
{
    int s = g_rowptr[node];
    int e = g_rowptr[node + 1];
    float4 acc = make_float4(0.f, 0.f, 0.f, 0.f);
    for (int j = s; j < e; ++j) {
        int   src = __ldg(&g_ecol[j]);
        float w   = __ldg(&g_ew[j]);
        uint2 v = __ldg(&hb[(size_t)src * F4 + f]);
        __nv_bfloat162 p0 = *reinterpret_cast<const __nv_bfloat162*>(&v.x);
        __nv_bfloat162 p1 = *reinterpret_cast<const __nv_bfloat162*>(&v.y);
        float2 f0 = __bfloat1622float2(p0);
        float2 f1 = __bfloat1622float2(p1);
        acc.x = fmaf(w, f0.x, acc.x);
        acc.y = fmaf(w, f0.y, acc.y);
        acc.z = fmaf(w, f1.x, acc.z);
        acc.w = fmaf(w, f1.y, acc.w);
    }
    float dw = g_diag[node];
    float4 hv = __ldg(&hs[(size_t)node * F4 + f]);
    acc.x = fmaf(dw, hv.x, acc.x);
    acc.y = fmaf(dw, hv.y, acc.y);
    acc.z = fmaf(dw, hv.z, acc.z);
    acc.w = fmaf(dw, hv.w, acc.w);
    if (mode) {
        float4 t = __ldg(&t0[(size_t)node * F4 + f]);
        acc.x = 2.f * acc.x - t.x;
        acc.y = 2.f * acc.y - t.y;
        acc.z = 2.f * acc.z - t.z;
        acc.w = 2.f * acc.w - t.w;
    }
    size_t idx = (size_t)node * F4 + f;
    out_r[idx] = make_float4(to_tf32(acc.x), to_tf32(acc.y), to_tf32(acc.z), to_tf32(acc.w));
    if (out_b) {
        __nv_bfloat162 b0 = __float22bfloat162_rn(make_float2(acc.x, acc.y));
        __nv_bfloat162 b1 = __float22bfloat162_rn(make_float2(acc.z, acc.w));
        uint2 u;
        u.x = *reinterpret_cast<uint32_t*>(&b0);
        u.y = *reinterpret_cast<uint32_t*>(&b1);
        out_b[idx] = u;
    }
}

__device__ __forceinline__ void spmm_b2_body(
    int node, int f, const uint32_t* __restrict__ hb, const float2* __restrict__ hs,
    const float2* __restrict__ t0, float2* __restrict__ out_r,
    uint32_t* __restrict__ out_b, int F2, int mode)
{
    int s = g_rowptr[node];
    int e = g_rowptr[node + 1];
    float2 acc = make_float2(0.f, 0.f);
    for (int j = s; j < e; ++j) {
        int   src = __ldg(&g_ecol[j]);
        float w   = __ldg(&g_ew[j]);
        uint32_t v = __ldg(&hb[(size_t)src * F2 + f]);
        float2 fv = __bfloat1622float2(*reinterpret_cast<const __nv_bfloat162*>(&v));
        acc.x = fmaf(w, fv.x, acc.x);
        acc.y = fmaf(w, fv.y, acc.y);
    }
    float dw = g_diag[node];
    float2 hv = __ldg(&hs[(size_t)node * F2 + f]);
    acc.x = fmaf(dw, hv.x, acc.x);
    acc.y = fmaf(dw, hv.y, acc.y);
    if (mode) {
        float2 t = __ldg(&t0[(size_t)node * F2 + f]);
        acc.x = 2.f * acc.x - t.x;
        acc.y = 2.f * acc.y - t.y;
    }
    size_t idx = (size_t)node * F2 + f;
    out_r[idx] = make_float2(to_tf32(acc.x), to_tf32(acc.y));
    if (out_b) {
        __nv_bfloat162 b = __float22bfloat162_rn(acc);
        out_b[idx] = *reinterpret_cast<uint32_t*>(&b);
    }
}

// ---------------- fused phase kernel: interleaved SpMM blocks + GEMM blocks ---
__device__ __forceinline__ void mma_tf32(float* c, const uint32_t* a, const uint32_t* b) {
    asm volatile(
        "mma.sync.aligned.m16n8k8.row.col.f32.tf32.tf32.f32 "
        "{%0,%1,%2,%3}, {%4,%5,%6,%7}, {%8,%9}, {%0,%1,%2,%3};"
        : "+f"(c[0]), "+f"(c[1]), "+f"(c[2]), "+f"(c[3])
        : "r"(a[0]), "r"(a[1]), "r"(a[2]), "r"(a[3]), "r"(b[0]), "r"(b[1]));
}

__device__ __forceinline__ void cp_async8(uint32_t dst, const void* src, int sz) {
    asm volatile("cp.async.ca.shared.global [%0], [%1], 8, %2;"
                 :: "r"(dst), "l"(src), "r"(sz));
}
__device__ __forceinline__ void cp_commit() { asm volatile("cp.async.commit_group;"); }
template<int N> __device__ __forceinline__ void cp_wait() {
    asm volatile("cp.async.wait_group %0;" :: "n"(N));
}

#define GBM 128
#define GBN 128
#define GBK 16
#define GST 3
#define ASTRIDE 20
#define BSTRIDE 136
#define GSMEM ((GST*GBM*ASTRIDE + GST*GBK*BSTRIDE) * 4)

__global__ __launch_bounds__(256, 2) void k_phase(
    // gemm args
    const float* __restrict__ A0, const float* __restrict__ A1, int nmat,
    const float* __restrict__ W, const float* __restrict__ bias,
    const float* __restrict__ accin, float* __restrict__ accout,
    float* __restrict__ out, float* __restrict__ out_r,
    __nv_bfloat16* __restrict__ out_b, int final_f,
    int K, int Nout, int gxdim, int ngemm,
    // spmm args
    const void* __restrict__ hb, const void* __restrict__ hs,
    const void* __restrict__ t0, void* __restrict__ sp_r, void* __restrict__ sp_b,
    int Fv, int smode, int svec,
    int ratio)
{
    int bid = blockIdx.x;
    int gq = bid / ratio;
    bool isg = (bid % ratio == 0) && (gq < ngemm);

    if (!isg) {
        // -------- SpMM block: 2 nodes, 128 feature-threads each --------
        int cnt = gq + 1; if (cnt > ngemm) cnt = ngemm;
        int idx = bid - cnt;
        int node = idx * 2 + (threadIdx.x >> 7);
        int f = threadIdx.x & 127;
        if (node < NNODES && f < Fv) {
            if (svec == 4)
                spmm_b4_body(node, f, (const uint2*)hb, (const float4*)hs,
                             (const float4*)t0, (float4*)sp_r, (uint2*)sp_b, Fv, smode);
            else
                spmm_b2_body(node, f, (const uint32_t*)hb, (const float2*)hs,
                             (const float2*)t0, (float2*)sp_r, (uint32_t*)sp_b, Fv, smode);
        }
        return;
    }

    // -------- GEMM block (R11 mainloop, nmat matrices) --------
    extern __shared__ float smem[];
    float* As = smem;
    float* Bs = smem + GST * GBM * ASTRIDE;
    uint32_t sA = (uint32_t)__cvta_generic_to_shared(As);
    uint32_t sB = (uint32_t)__cvta_generic_to_shared(Bs);

    int tid  = threadIdx.x;
    int wid  = tid >> 5;
    int lane = tid & 31;
    int g    = lane >> 2;
    int tig  = lane & 3;
    int wm   = wid & 1;
    int wn   = wid >> 1;
    int bm   = (gq / gxdim) * GBM;
    int bn   = (gq % gxdim) * GBN;
    const int M = NNODES;

    int kt = (K + GBK - 1) / GBK;
    int nt = nmat * kt;
    const float* Amats[2] = {A0, A1 ? A1 : A0};

    float acc[4][4][4];
    #pragma unroll
    for (int mi = 0; mi < 4; ++mi)
        #pragma unroll
        for (int ni = 0; ni < 4; ++ni)
            #pragma unroll
            for (int r = 0; r < 4; ++r) acc[mi][ni][r] = 0.0f;

    auto issue_tile = [&](int t) {
        int pn = t / kt;
        int k0 = (t - pn * kt) * GBK;
        int s  = t % GST;
        const float* A = Amats[pn];
        #pragma unroll
        for (int q = 0; q < 4; ++q) {
            int p  = q * 256 + tid;
            int m  = p >> 3;
            int kk = (p & 7) * 2;
            int gm = bm + m, gk = k0 + kk;
            int sz = (gm < M && gk < K) ? 8 : 0;
            const float* src = sz ? (A + (size_t)gm * K + gk) : A;
            uint32_t dst = sA + (uint32_t)(((s * GBM + m) * ASTRIDE + kk) * 4);
            cp_async8(dst, src, sz);
        }
        const float* B = W + (size_t)pn * K * Nout;
        #pragma unroll
        for (int q = 0; q < 4; ++q) {
            int p  = q * 256 + tid;
            int r  = p >> 6;
            int n0 = (p & 63) * 2;
            int gk = k0 + r, gn = bn + n0;
            int sz = (gk < K && gn < Nout) ? 8 : 0;
            const float* src = sz ? (B + (size_t)gk * Nout + gn) : B;
            uint32_t dst = sB + (uint32_t)(((s * GBK + r) * BSTRIDE + n0) * 4);
            cp_async8(dst, src, sz);
        }
    };

    #pragma unroll
    for (int t = 0; t < GST - 1; ++t) {
        issue_tile(t);
        cp_commit();
    }

    for (int t = 0; t < nt; ++t) {
        cp_wait<GST - 2>();
        __syncthreads();

        int tn = t + GST - 1;
        if (tn < nt) issue_tile(tn);
        cp_commit();

        int s = t % GST;
        const float* Ab = As + s * GBM * ASTRIDE;
        const float* Bb = Bs + s * GBK * BSTRIDE;
        #pragma unroll
        for (int ks = 0; ks < GBK; ks += 8) {
            uint32_t af[4][4];
            uint32_t bf[4][2];
            #pragma unroll
            for (int mi = 0; mi < 4; ++mi) {
                int mb = wm * 64 + mi * 16;
                af[mi][0] = __float_as_uint(Ab[(mb + g    ) * ASTRIDE + ks + tig    ]);
                af[mi][1] = __float_as_uint(Ab[(mb + g + 8) * ASTRIDE + ks + tig    ]);
                af[mi][2] = __float_as_uint(Ab[(mb + g    ) * ASTRIDE + ks + tig + 4]);
                af[mi][3] = __float_as_uint(Ab[(mb + g + 8) * ASTRIDE + ks + tig + 4]);
            }
            #pragma unroll
            for (int ni = 0; ni < 4; ++ni) {
                int nb = wn * 32 + ni * 8;
                bf[ni][0] = __float_as_uint(Bb[(ks + tig    ) * BSTRIDE + nb + g]);
                bf[ni][1] = __float_as_uint(Bb[(ks + tig + 4) * BSTRIDE + nb + g]);
            }
            #pragma unroll
            for (int mi = 0; mi < 4; ++mi)
                #pragma unroll
                for (int ni = 0; ni < 4; ++ni)
                    mma_tf32(acc[mi][ni], af[mi], bf[ni]);
        }
        __syncthreads();
    }

    // ---- epilogue: accumulate chain; final -> bias+relu+outputs ----
    #pragma unroll
    for (int mi = 0; mi < 4; ++mi) {
        int r0 = bm + wm * 64 + mi * 16 + g;
        int r1 = r0 + 8;
        #pragma unroll
        for (int ni = 0; ni < 4; ++ni) {
            int c0 = bn + wn * 32 + ni * 8 + 2 * tig;
            if (c0 >= Nout) continue;          // Nout even -> pair all-or-nothing
            float bv0 = final_f ? bias[c0]     : 0.0f;
            float bv1 = final_f ? bias[c0 + 1] : 0.0f;
            #pragma unroll
            for (int h = 0; h < 2; ++h) {
                int r = h ? r1 : r0;
                if (r >= M) continue;
                size_t o = (size_t)r * Nout + c0;
                float v0 = acc[mi][ni][2 * h]     + bv0;
                float v1 = acc[mi][ni][2 * h + 1] + bv1;
                if (accin) { v0 += accin[o]; v1 += accin[o + 1]; }
                if (final_f) {
                    v0 = v0 > 0.f ? v0 : 0.f;
                    v1 = v1 > 0.f ? v1 : 0.f;
                    out[o] = v0; out[o + 1] = v1;
                    if (out_r) { out_r[o] = to_tf32(v0); out_r[o + 1] = to_tf32(v1); }
                    if (out_b) {
                        __nv_bfloat162 b = __float22bfloat162_rn(make_float2(v0, v1));
                        *reinterpret_cast<uint32_t*>(out_b + o) = *reinterpret_cast<uint32_t*>(&b);
                    }
                } else {
                    accout[o] = v0; accout[o + 1] = v1;
                }
            }
        }
    }
}

// ---------------- host side ----------------
static inline int ceil_div(int a, int b) { return (a + b - 1) / b; }

static void launch_phase(
    int nspmm, const void* hb, const void* hs, const void* t0,
    void* sp_r, void* sp_b, int Fv, int smode, int svec,
    const float* A0, const float* A1, int nmat, const float* W,
    const float* bias, const float* accin, float* accout,
    float* out, float* out_r, __nv_bfloat16* out_b, int final_f,
    int K, int Nout)
{
    int gx = ceil_div(Nout, GBN), gy = ceil_div(NNODES, GBM);
    int ngemm = gx * gy;
    int total = nspmm + ngemm;
    int ratio = nspmm ? (total / ngemm) : 1;
    if (ratio < 1) ratio = 1;
    k_phase<<<total, 256, GSMEM>>>(
        A0, A1, nmat, W, bias, accin, accout, out, out_r, out_b, final_f,
        K, Nout, gx, ngemm,
        hb, hs, t0, sp_r, sp_b, Fv, smode, svec, ratio);
}

extern "C" void kernel_launch(void* const* d_in, const int* in_sizes, int n_in,
                              void* d_out, int out_size) {
    const float* x  = (const float*)d_in[0];
    const void*  ei = d_in[1];
    const float* w1 = (const float*)d_in[2];
    const float* b1 = (const float*)d_in[3];
    const float* w2 = (const float*)d_in[4];
    const float* b2 = (const float*)d_in[5];
    const float* w3 = (const float*)d_in[6];
    const float* b3 = (const float*)d_in[7];
    float* out = (float*)d_out;

    static bool attr_set = false;
    if (!attr_set) {
        cudaFuncSetAttribute(k_phase, cudaFuncAttributeMaxDynamicSharedMemorySize, GSMEM);
        attr_set = true;
    }

    float *T1r, *T2r, *acc, *h1, *h1r, *h2, *h2r, *xr, *W1r, *W2r, *W3r;
    __nv_bfloat16 *xb, *T1b, *h1b, *h2b;
    cudaGetSymbolAddress((void**)&T1r, g_T1r);
    cudaGetSymbolAddress((void**)&T2r, g_T2r);
    cudaGetSymbolAddress((void**)&acc, g_acc);
    cudaGetSymbolAddress((void**)&h1,  g_h1);
    cudaGetSymbolAddress((void**)&h1r, g_h1r);
    cudaGetSymbolAddress((void**)&h2,  g_h2);
    cudaGetSymbolAddress((void**)&h2r, g_h2r);
    cudaGetSymbolAddress((void**)&xr,  g_xr);
    cudaGetSymbolAddress((void**)&W1r, g_W1r);
    cudaGetSymbolAddress((void**)&W2r, g_W2r);
    cudaGetSymbolAddress((void**)&W3r, g_W3r);
    cudaGetSymbolAddress((void**)&xb,  g_xb);
    cudaGetSymbolAddress((void**)&T1b, g_T1b);
    cudaGetSymbolAddress((void**)&h1b, g_h1b);
    cudaGetSymbolAddress((void**)&h2b, g_h2b);

    const int NSP = NNODES / 2;   // 25000 spmm blocks (2 nodes each)

    // graph setup
    k_detect<<<1, 512>>>((const int*)ei);
    k_init<<<ceil_div(NNODES, 256), 256>>>();
    k_degree<<<ceil_div(NEDGES, 256), 256>>>(ei);
    k_node<<<ceil_div(NNODES, 256), 256>>>();
    k_scan<<<1, 1024>>>();
    k_scatter<<<ceil_div(NEDGES, 256), 256>>>(ei);

    // operand prep
    k_round_dual<<<ceil_div(NNODES * 512, 256), 256>>>(x, xr, xb, NNODES * 512);
    k_round<<<ceil_div(3 * 512 * 250, 256), 256>>>(w1, W1r, 3 * 512 * 250);
    k_round<<<ceil_div(3 * 250 * 500, 256), 256>>>(w2, W2r, 3 * 250 * 500);
    k_round<<<ceil_div(3 * 500 * 1000, 256), 256>>>(w3, W3r, 3 * 500 * 1000);

    // ---- layer 1: Fin=512 (F4=128, vec4), Fout=250 ----
    launch_phase(NSP, xb, x, nullptr, T1r, T1b, 128, 0, 4,
                 xr, nullptr, 1, W1r, nullptr, nullptr, acc,
                 nullptr, nullptr, nullptr, 0, 512, 250);
    launch_phase(NSP, T1b, T1r, x, T2r, nullptr, 128, 1, 4,
                 T1r, nullptr, 1, W1r + (size_t)1 * 512 * 250, nullptr, acc, acc,
                 nullptr, nullptr, nullptr, 0, 512, 250);
    launch_phase(0, nullptr, nullptr, nullptr, nullptr, nullptr, 0, 0, 4,
                 T2r, nullptr, 1, W1r + (size_t)2 * 512 * 250, b1, acc, nullptr,
                 h1, h1r, h1b, 1, 512, 250);

    // ---- layer 2: Fin=250 (F2=125, vec2), Fout=500 ----
    launch_phase(NSP, h1b, h1, nullptr, T1r, T1b, 125, 0, 2,
                 h1r, nullptr, 1, W2r, nullptr, nullptr, acc,
                 nullptr, nullptr, nullptr, 0, 250, 500);
    launch_phase(NSP, T1b, T1r, h1, T2r, nullptr, 125, 1, 2,
                 T1r, nullptr, 1, W2r + (size_t)1 * 250 * 500, nullptr, acc, acc,
                 nullptr, nullptr, nullptr, 0, 250, 500);
    launch_phase(0, nullptr, nullptr, nullptr, nullptr, nullptr, 0, 0, 2,
                 T2r, nullptr, 1, W2r + (size_t)2 * 250 * 500, b2, acc, nullptr,
                 h2, h2r, h2b, 1, 250, 500);

    // ---- layer 3: Fin=500 (F4=125, vec4), Fout=1000 ----
    launch_phase(NSP, h2b, h2, nullptr, T1r, T1b, 125, 0, 4,
                 h2r, nullptr, 1, W3r, nullptr, nullptr, acc,
                 nullptr, nullptr, nullptr, 0, 500, 1000);
    launch_phase(NSP, T1b, T1r, h2, T2r, nullptr, 125, 1, 4,
                 T1r, nullptr, 1, W3r + (size_t)1 * 500 * 1000, nullptr, acc, acc,
                 nullptr, nullptr, nullptr, 0, 500, 1000);
    launch_phase(0, nullptr, nullptr, nullptr, nullptr, nullptr, 0, 0, 4,
                 T2r, nullptr, 1, W3r + (size_t)2 * 500 * 1000, b3, acc, nullptr,
                 out, nullptr, nullptr, 1, 500, 1000);
}

// round 14
// speedup vs baseline: 1.8798x; 1.8798x over previous
#include <cuda_runtime.h>
#include <cuda_bf16.h>
#include <cstdint>

#define NNODES 50000
#define NEDGES 1600000
#define MAXF   512

// ---------------- device scratch (static, no allocation) ----------------
__device__ int   g_flag;
__device__ int   g_deg[NNODES];
__device__ float g_dinv[NNODES];
__device__ float g_diag[NNODES];
__device__ int   g_rowptr[NNODES + 1];
__device__ int   g_cursor[NNODES];
__device__ int   g_ecol[NEDGES];
__device__ float g_ew[NEDGES];
__device__ float g_T1r[(size_t)NNODES * MAXF];
__device__ float g_T2r[(size_t)NNODES * MAXF];
__device__ float g_acc[(size_t)NNODES * 250];     // layer-1 y2
__device__ float g_v  [(size_t)NNODES * 250];     // layer-1 v
__device__ float g_h1 [(size_t)NNODES * 250];
__device__ float g_h1r[(size_t)NNODES * 250];
__device__ float g_h2 [(size_t)NNODES * 500];
__device__ float g_h2r[(size_t)NNODES * 500];
__device__ float g_xr [(size_t)NNODES * 512];
__device__ float g_W1r[3 * 512 * 250];
__device__ float g_W2r[3 * 250 * 500];
__device__ float g_W3r[3 * 500 * 1000];
// bf16 gather copies
__device__ __nv_bfloat16 g_y2b[(size_t)NNODES * 250];
__device__ __nv_bfloat16 g_T1b[(size_t)NNODES * MAXF];
__device__ __nv_bfloat16 g_h1b[(size_t)NNODES * 250];
__device__ __nv_bfloat16 g_h2b[(size_t)NNODES * 500];

__device__ __forceinline__ float to_tf32(float x) {
    float y;
    asm("cvt.rna.tf32.f32 %0, %1;" : "=f"(y) : "f"(x));
    return y;
}

// ---------------- index width detection (parallel) ----------------
__global__ void k_detect(const int* e32) {
    __shared__ int ok;
    if (threadIdx.x == 0) ok = 1;
    __syncthreads();
    if (e32[2 * threadIdx.x + 1] != 0) ok = 0;   // benign race: only writes 0
    __syncthreads();
    if (threadIdx.x == 0) g_flag = ok;
}

__device__ __forceinline__ int load_idx(const void* e, long long i) {
    if (g_flag) return (int)((const long long*)e)[i];
    return ((const int*)e)[i];
}

// ---------------- graph setup ----------------
__global__ void k_init() {
    int i = blockIdx.x * blockDim.x + threadIdx.x;
    if (i < NNODES) { g_deg[i] = 0; g_cursor[i] = 0; }
}

__global__ void k_degree(const void* e) {
    int i = blockIdx.x * blockDim.x + threadIdx.x;
    if (i < NEDGES) {
        int dst = load_idx(e, (long long)NEDGES + i);
        atomicAdd(&g_deg[dst], 1);
    }
}

__global__ void k_node() {
    int i = blockIdx.x * blockDim.x + threadIdx.x;
    if (i < NNODES) {
        int d = g_deg[i];
        g_dinv[i] = d > 0 ? rsqrtf((float)d) : 0.0f;
        g_diag[i] = d > 0 ? 0.0f : -1.0f;
    }
}

__global__ void k_scan() {
    __shared__ int warp_sums[32];
    int tid  = threadIdx.x;
    int lane = tid & 31;
    int wid  = tid >> 5;
    int carry = 0;
    for (int base = 0; base < NNODES; base += 1024) {
        int i = base + tid;
        int v = (i < NNODES) ? g_deg[i] : 0;
        int x = v;
        #pragma unroll
        for (int o = 1; o < 32; o <<= 1) {
            int y = __shfl_up_sync(0xffffffffu, x, o);
            if (lane >= o) x += y;
        }
        if (lane == 31) warp_sums[wid] = x;
        __syncthreads();
        if (tid < 32) {
            int s = warp_sums[tid];
            #pragma unroll
            for (int o = 1; o < 32; o <<= 1) {
                int y = __shfl_up_sync(0xffffffffu, s, o);
                if (tid >= o) s += y;
            }
            warp_sums[tid] = s;
        }
        __syncthreads();
        int incl = x + (wid > 0 ? warp_sums[wid - 1] : 0);
        if (i < NNODES) g_rowptr[i] = carry + incl - v;
        int total = warp_sums[31];
        __syncthreads();
        carry += total;
    }
    if (tid == 0) g_rowptr[NNODES] = carry;
}

__global__ void k_scatter(const void* e) {
    int i = blockIdx.x * blockDim.x + threadIdx.x;
    if (i < NEDGES) {
        int src = load_idx(e, i);
        int dst = load_idx(e, (long long)NEDGES + i);
        float w = -g_dinv[dst] * g_dinv[src];
        int pos = g_rowptr[dst] + atomicAdd(&g_cursor[dst], 1);
        g_ecol[pos] = src;
        g_ew[pos]   = w;
    }
}

// ---------------- rounding helper ----------------
__global__ void k_round(const float* __restrict__ in, float* __restrict__ dst, int n) {
    int i = blockIdx.x * blockDim.x + threadIdx.x;
    if (i < n) dst[i] = to_tf32(in[i]);
}

// ---------------- bf16-gather SpMM (layers 2/3, unchanged from R11) ----------
__global__ void k_spmm_b4(const uint2* __restrict__ hb, const float4* __restrict__ hs,
                          const float4* __restrict__ t0,
                          float4* __restrict__ out, float4* __restrict__ out_r,
                          uint2* __restrict__ out_b, int F4, int mode) {
    int node = blockIdx.x;
    int f = threadIdx.x;
    if (f >= F4) return;
    int s = g_rowptr[node];
    int e = g_rowptr[node + 1];
    float4 acc = make_float4(0.f, 0.f, 0.f, 0.f);
    for (int j = s; j < e; ++j) {
        int   src = __ldg(&g_ecol[j]);
        float w   = __ldg(&g_ew[j]);
        uint2 v = __ldg(&hb[(size_t)src * F4 + f]);
        __nv_bfloat162 p0 = *reinterpret_cast<const __nv_bfloat162*>(&v.x);
        __nv_bfloat162 p1 = *reinterpret_cast<const __nv_bfloat162*>(&v.y);
        float2 f0 = __bfloat1622float2(p0);
        float2 f1 = __bfloat1622float2(p1);
        acc.x = fmaf(w, f0.x, acc.x);
        acc.y = fmaf(w, f0.y, acc.y);
        acc.z = fmaf(w, f1.x, acc.z);
        acc.w = fmaf(w, f1.y, acc.w);
    }
    float dw = g_diag[node];
    float4 hv = __ldg(&hs[(size_t)node * F4 + f]);
    acc.x = fmaf(dw, hv.x, acc.x);
    acc.y = fmaf(dw, hv.y, acc.y);
    acc.z = fmaf(dw, hv.z, acc.z);
    acc.w = fmaf(dw, hv.w, acc.w);
    if (mode) {
        float4 t = __ldg(&t0[(size_t)node * F4 + f]);
        acc.x = 2.f * acc.x - t.x;
        acc.y = 2.f * acc.y - t.y;
        acc.z = 2.f * acc.z - t.z;
        acc.w = 2.f * acc.w - t.w;
    }
    size_t idx = (size_t)node * F4 + f;
    if (out) out[idx] = acc;
    if (out_r) out_r[idx] =
        make_float4(to_tf32(acc.x), to_tf32(acc.y), to_tf32(acc.z), to_tf32(acc.w));
    if (out_b) {
        __nv_bfloat162 b0 = __float22bfloat162_rn(make_float2(acc.x, acc.y));
        __nv_bfloat162 b1 = __float22bfloat162_rn(make_float2(acc.z, acc.w));
        uint2 u;
        u.x = *reinterpret_cast<uint32_t*>(&b0);
        u.y = *reinterpret_cast<uint32_t*>(&b1);
        out_b[idx] = u;
    }
}

__global__ void k_spmm_b2(const uint32_t* __restrict__ hb, const float2* __restrict__ hs,
                          const float2* __restrict__ t0,
                          float2* __restrict__ out, float2* __restrict__ out_r,
                          uint32_t* __restrict__ out_b, int F2, int mode) {
    int node = blockIdx.x;
    int f = threadIdx.x;
    if (f >= F2) return;
    int s = g_rowptr[node];
    int e = g_rowptr[node + 1];
    float2 acc = make_float2(0.f, 0.f);
    for (int j = s; j < e; ++j) {
        int   src = __ldg(&g_ecol[j]);
        float w   = __ldg(&g_ew[j]);
        uint32_t v = __ldg(&hb[(size_t)src * F2 + f]);
        float2 fv = __bfloat1622float2(*reinterpret_cast<const __nv_bfloat162*>(&v));
        acc.x = fmaf(w, fv.x, acc.x);
        acc.y = fmaf(w, fv.y, acc.y);
    }
    float dw = g_diag[node];
    float2 hv = __ldg(&hs[(size_t)node * F2 + f]);
    acc.x = fmaf(dw, hv.x, acc.x);
    acc.y = fmaf(dw, hv.y, acc.y);
    if (mode) {
        float2 t = __ldg(&t0[(size_t)node * F2 + f]);
        acc.x = 2.f * acc.x - t.x;
        acc.y = 2.f * acc.y - t.y;
    }
    size_t idx = (size_t)node * F2 + f;
    if (out) out[idx] = acc;
    if (out_r) out_r[idx] = make_float2(to_tf32(acc.x), to_tf32(acc.y));
    if (out_b) {
        __nv_bfloat162 b = __float22bfloat162_rn(acc);
        out_b[idx] = *reinterpret_cast<uint32_t*>(&b);
    }
}

// ---------------- layer-1 commuted SpMMs (250 features, vec2) ----------------
// v = y1 + 2*(gather(y2b) + diag*y2)
__global__ void k_l1a(const uint32_t* __restrict__ y2b, const float2* __restrict__ y2,
                      const float2* __restrict__ y1,
                      float2* __restrict__ v, uint32_t* __restrict__ vb) {
    int node = blockIdx.x;
    int f = threadIdx.x;
    if (f >= 125) return;
    int s = g_rowptr[node];
    int e = g_rowptr[node + 1];
    float2 acc = make_float2(0.f, 0.f);
    for (int j = s; j < e; ++j) {
        int   src = __ldg(&g_ecol[j]);
        float w   = __ldg(&g_ew[j]);
        uint32_t u = __ldg(&y2b[(size_t)src * 125 + f]);
        float2 fv = __bfloat1622float2(*reinterpret_cast<const __nv_bfloat162*>(&u));
        acc.x = fmaf(w, fv.x, acc.x);
        acc.y = fmaf(w, fv.y, acc.y);
    }
    size_t idx = (size_t)node * 125 + f;
    float dw = g_diag[node];
    float2 s2 = __ldg(&y2[idx]);
    acc.x = fmaf(dw, s2.x, acc.x);
    acc.y = fmaf(dw, s2.y, acc.y);
    float2 a1 = __ldg(&y1[idx]);
    float2 vv = make_float2(a1.x + 2.f * acc.x, a1.y + 2.f * acc.y);
    v[idx] = vv;
    __nv_bfloat162 b = __float22bfloat162_rn(vv);
    vb[idx] = *reinterpret_cast<uint32_t*>(&b);
}

// h1 = relu(y0 - y2 + gather(vb) + diag*v + bias); dual tf32/bf16 outputs
__global__ void k_l1b(const uint32_t* __restrict__ vb, const float2* __restrict__ v,
                      const float2* __restrict__ y0, const float2* __restrict__ y2,
                      const float* __restrict__ bias,
                      float2* __restrict__ h1, float2* __restrict__ h1r,
                      uint32_t* __restrict__ h1b) {
    int node = blockIdx.x;
    int f = threadIdx.x;
    if (f >= 125) return;
    int s = g_rowptr[node];
    int e = g_rowptr[node + 1];
    float2 acc = make_float2(0.f, 0.f);
    for (int j = s; j < e; ++j) {
        int   src = __ldg(&g_ecol[j]);
        float w   = __ldg(&g_ew[j]);
        uint32_t u = __ldg(&vb[(size_t)src * 125 + f]);
        float2 fv = __bfloat1622float2(*reinterpret_cast<const __nv_bfloat162*>(&u));
        acc.x = fmaf(w, fv.x, acc.x);
        acc.y = fmaf(w, fv.y, acc.y);
    }
    size_t idx = (size_t)node * 125 + f;
    float dw = g_diag[node];
    float2 sv = __ldg(&v[idx]);
    acc.x = fmaf(dw, sv.x, acc.x);
    acc.y = fmaf(dw, sv.y, acc.y);
    float2 a0 = __ldg(&y0[idx]);
    float2 a2 = __ldg(&y2[idx]);
    float b0 = bias[2 * f], b1 = bias[2 * f + 1];
    float o0 = a0.x - a2.x + acc.x + b0;
    float o1 = a0.y - a2.y + acc.y + b1;
    o0 = o0 > 0.f ? o0 : 0.f;
    o1 = o1 > 0.f ? o1 : 0.f;
    h1[idx] = make_float2(o0, o1);
    h1r[idx] = make_float2(to_tf32(o0), to_tf32(o1));
    __nv_bfloat162 b = __float22bfloat162_rn(make_float2(o0, o1));
    h1b[idx] = *reinterpret_cast<uint32_t*>(&b);
}

// ---------------- TF32 GEMM core (R11 mainloop, unchanged) -------------------
__device__ __forceinline__ void mma_tf32(float* c, const uint32_t* a, const uint32_t* b) {
    asm volatile(
        "mma.sync.aligned.m16n8k8.row.col.f32.tf32.tf32.f32 "
        "{%0,%1,%2,%3}, {%4,%5,%6,%7}, {%8,%9}, {%0,%1,%2,%3};"
        : "+f"(c[0]), "+f"(c[1]), "+f"(c[2]), "+f"(c[3])
        : "r"(a[0]), "r"(a[1]), "r"(a[2]), "r"(a[3]), "r"(b[0]), "r"(b[1]));
}

__device__ __forceinline__ void cp_async8(uint32_t dst, const void* src, int sz) {
    asm volatile("cp.async.ca.shared.global [%0], [%1], 8, %2;"
                 :: "r"(dst), "l"(src), "r"(sz));
}
__device__ __forceinline__ void cp_commit() { asm volatile("cp.async.commit_group;"); }
template<int N> __device__ __forceinline__ void cp_wait() {
    asm volatile("cp.async.wait_group %0;" :: "n"(N));
}

#define GBM 128
#define GBN 128
#define GBK 16
#define GST 3
#define ASTRIDE 20
#define BSTRIDE 136
#define GSMEM ((GST*GBM*ASTRIDE + GST*GBK*BSTRIDE) * 4)

// mainloop shared by both GEMM kernels; accumulates nmat matrices
template<int NMAT>
__device__ __forceinline__ void gemm_mainloop(
    const float* A0, const float* A1, const float* A2, const float* W,
    int M, int K, int Nout, int bm, int bn, float acc[4][4][4])
{
    extern __shared__ float smem[];
    float* As = smem;
    float* Bs = smem + GST * GBM * ASTRIDE;
    uint32_t sA = (uint32_t)__cvta_generic_to_shared(As);
    uint32_t sB = (uint32_t)__cvta_generic_to_shared(Bs);

    int tid  = threadIdx.x;
    int wid  = tid >> 5;
    int lane = tid & 31;
    int g    = lane >> 2;
    int tig  = lane & 3;
    int wm   = wid & 1;
    int wn   = wid >> 1;

    int kt = (K + GBK - 1) / GBK;
    int nt = NMAT * kt;

    auto issue_tile = [&](int t) {
        int pn = t / kt;
        int k0 = (t - pn * kt) * GBK;
        int s  = t % GST;
        const float* A = (pn == 0) ? A0 : ((pn == 1) ? A1 : A2);
        #pragma unroll
        for (int q = 0; q < 4; ++q) {
            int p  = q * 256 + tid;
            int m  = p >> 3;
            int kk = (p & 7) * 2;
            int gm = bm + m, gk = k0 + kk;
            int sz = (gm < M && gk < K) ? 8 : 0;
            const float* src = sz ? (A + (size_t)gm * K + gk) : A;
            uint32_t dst = sA + (uint32_t)(((s * GBM + m) * ASTRIDE + kk) * 4);
            cp_async8(dst, src, sz);
        }
        const float* B = W + (size_t)pn * K * Nout;
        #pragma unroll
        for (int q = 0; q < 4; ++q) {
            int p  = q * 256 + tid;
            int r  = p >> 6;
            int n0 = (p & 63) * 2;
            int gk = k0 + r, gn = bn + n0;
            int sz = (gk < K && gn < Nout) ? 8 : 0;
            const float* src = sz ? (B + (size_t)gk * Nout + gn) : B;
            uint32_t dst = sB + (uint32_t)(((s * GBK + r) * BSTRIDE + n0) * 4);
            cp_async8(dst, src, sz);
        }
    };

    #pragma unroll
    for (int t = 0; t < GST - 1; ++t) {
        issue_tile(t);
        cp_commit();
    }

    for (int t = 0; t < nt; ++t) {
        cp_wait<GST - 2>();
        __syncthreads();

        int tn = t + GST - 1;
        if (tn < nt) issue_tile(tn);
        cp_commit();

        int s = t % GST;
        const float* Ab = As + s * GBM * ASTRIDE;
        const float* Bb = Bs + s * GBK * BSTRIDE;
        #pragma unroll
        for (int ks = 0; ks < GBK; ks += 8) {
            uint32_t af[4][4];
            uint32_t bf[4][2];
            #pragma unroll
            for (int mi = 0; mi < 4; ++mi) {
                int mb = wm * 64 + mi * 16;
                af[mi][0] = __float_as_uint(Ab[(mb + g    ) * ASTRIDE + ks + tig    ]);
                af[mi][1] = __float_as_uint(Ab[(mb + g + 8) * ASTRIDE + ks + tig    ]);
                af[mi][2] = __float_as_uint(Ab[(mb + g    ) * ASTRIDE + ks + tig + 4]);
                af[mi][3] = __float_as_uint(Ab[(mb + g + 8) * ASTRIDE + ks + tig + 4]);
            }
            #pragma unroll
            for (int ni = 0; ni < 4; ++ni) {
                int nb = wn * 32 + ni * 8;
                bf[ni][0] = __float_as_uint(Bb[(ks + tig    ) * BSTRIDE + nb + g]);
                bf[ni][1] = __float_as_uint(Bb[(ks + tig + 4) * BSTRIDE + nb + g]);
            }
            #pragma unroll
            for (int mi = 0; mi < 4; ++mi)
                #pragma unroll
                for (int ni = 0; ni < 4; ++ni)
                    mma_tf32(acc[mi][ni], af[mi], bf[ni]);
        }
        __syncthreads();
    }
}

// 3-matrix fused GEMM + bias + relu + dual outputs (layers 2/3)
__global__ __launch_bounds__(256, 2) void k_gemm3_tc(
    const float* __restrict__ A0, const float* __restrict__ A1,
    const float* __restrict__ A2, const float* __restrict__ W,
    const float* __restrict__ bias, float* __restrict__ out,
    float* __restrict__ out_r, __nv_bfloat16* __restrict__ out_b,
    int M, int K, int Nout)
{
    int bm = blockIdx.y * GBM;
    int bn = blockIdx.x * GBN;
    float acc[4][4][4];
    #pragma unroll
    for (int mi = 0; mi < 4; ++mi)
        #pragma unroll
        for (int ni = 0; ni < 4; ++ni)
            #pragma unroll
            for (int r = 0; r < 4; ++r) acc[mi][ni][r] = 0.0f;

    gemm_mainloop<3>(A0, A1, A2, W, M, K, Nout, bm, bn, acc);

    int tid  = threadIdx.x;
    int wid  = tid >> 5;
    int lane = tid & 31;
    int g    = lane >> 2;
    int tig  = lane & 3;
    int wm   = wid & 1;
    int wn   = wid >> 1;

    #pragma unroll
    for (int mi = 0; mi < 4; ++mi) {
        int r0 = bm + wm * 64 + mi * 16 + g;
        int r1 = r0 + 8;
        #pragma unroll
        for (int ni = 0; ni < 4; ++ni) {
            int c0 = bn + wn * 32 + ni * 8 + 2 * tig;
            if (c0 >= Nout) continue;
            float bv0 = bias[c0];
            float bv1 = bias[c0 + 1];
            if (r0 < M) {
                float v0 = acc[mi][ni][0] + bv0; v0 = v0 > 0.f ? v0 : 0.f;
                float v1 = acc[mi][ni][1] + bv1; v1 = v1 > 0.f ? v1 : 0.f;
                size_t o = (size_t)r0 * Nout + c0;
                out[o] = v0; out[o + 1] = v1;
                if (out_r) { out_r[o] = to_tf32(v0); out_r[o + 1] = to_tf32(v1); }
                if (out_b) {
                    __nv_bfloat162 b = __float22bfloat162_rn(make_float2(v0, v1));
                    *reinterpret_cast<uint32_t*>(out_b + o) = *reinterpret_cast<uint32_t*>(&b);
                }
            }
            if (r1 < M) {
                float v0 = acc[mi][ni][2] + bv0; v0 = v0 > 0.f ? v0 : 0.f;
                float v1 = acc[mi][ni][3] + bv1; v1 = v1 > 0.f ? v1 : 0.f;
                size_t o = (size_t)r1 * Nout + c0;
                out[o] = v0; out[o + 1] = v1;
                if (out_r) { out_r[o] = to_tf32(v0); out_r[o + 1] = to_tf32(v1); }
                if (out_b) {
                    __nv_bfloat162 b = __float22bfloat162_rn(make_float2(v0, v1));
                    *reinterpret_cast<uint32_t*>(out_b + o) = *reinterpret_cast<uint32_t*>(&b);
                }
            }
        }
    }
}

// 1-matrix GEMM, raw fp32 output (+ optional bf16) — layer-1 y_p = x@W_p
__global__ __launch_bounds__(256, 2) void k_gemm1_tc(
    const float* __restrict__ A0, const float* __restrict__ W,
    float* __restrict__ out, __nv_bfloat16* __restrict__ out_b,
    int M, int K, int Nout)
{
    int bm = blockIdx.y * GBM;
    int bn = blockIdx.x * GBN;
    float acc[4][4][4];
    #pragma unroll
    for (int mi = 0; mi < 4; ++mi)
        #pragma unroll
        for (int ni = 0; ni < 4; ++ni)
            #pragma unroll
            for (int r = 0; r < 4; ++r) acc[mi][ni][r] = 0.0f;

    gemm_mainloop<1>(A0, A0, A0, W, M, K, Nout, bm, bn, acc);

    int tid  = threadIdx.x;
    int wid  = tid >> 5;
    int lane = tid & 31;
    int g    = lane >> 2;
    int tig  = lane & 3;
    int wm   = wid & 1;
    int wn   = wid >> 1;

    #pragma unroll
    for (int mi = 0; mi < 4; ++mi) {
        int r0 = bm + wm * 64 + mi * 16 + g;
        int r1 = r0 + 8;
        #pragma unroll
        for (int ni = 0; ni < 4; ++ni) {
            int c0 = bn + wn * 32 + ni * 8 + 2 * tig;
            if (c0 >= Nout) continue;
            if (r0 < M) {
                size_t o = (size_t)r0 * Nout + c0;
                float v0 = acc[mi][ni][0], v1 = acc[mi][ni][1];
                out[o] = v0; out[o + 1] = v1;
                if (out_b) {
                    __nv_bfloat162 b = __float22bfloat162_rn(make_float2(v0, v1));
                    *reinterpret_cast<uint32_t*>(out_b + o) = *reinterpret_cast<uint32_t*>(&b);
                }
            }
            if (r1 < M) {
                size_t o = (size_t)r1 * Nout + c0;
                float v0 = acc[mi][ni][2], v1 = acc[mi][ni][3];
                out[o] = v0; out[o + 1] = v1;
                if (out_b) {
                    __nv_bfloat162 b = __float22bfloat162_rn(make_float2(v0, v1));
                    *reinterpret_cast<uint32_t*>(out_b + o) = *reinterpret_cast<uint32_t*>(&b);
                }
            }
        }
    }
}

// ---------------- host side ----------------
static inline int ceil_div(int a, int b) { return (a + b - 1) / b; }

extern "C" void kernel_launch(void* const* d_in, const int* in_sizes, int n_in,
                              void* d_out, int out_size) {
    const float* x  = (const float*)d_in[0];
    const void*  ei = d_in[1];
    const float* w1 = (const float*)d_in[2];
    const float* b1 = (const float*)d_in[3];
    const float* w2 = (const float*)d_in[4];
    const float* b2 = (const float*)d_in[5];
    const float* w3 = (const float*)d_in[6];
    const float* b3 = (const float*)d_in[7];
    float* out = (float*)d_out;

    static bool attr_set = false;
    if (!attr_set) {
        cudaFuncSetAttribute(k_gemm3_tc, cudaFuncAttributeMaxDynamicSharedMemorySize, GSMEM);
        cudaFuncSetAttribute(k_gemm1_tc, cudaFuncAttributeMaxDynamicSharedMemorySize, GSMEM);
        attr_set = true;
    }

    float *T1r, *T2r, *acc, *vbuf, *h1, *h1r, *h2, *h2r, *xr, *W1r, *W2r, *W3r;
    __nv_bfloat16 *y2b, *T1b, *h1b, *h2b;
    cudaGetSymbolAddress((void**)&T1r, g_T1r);
    cudaGetSymbolAddress((void**)&T2r, g_T2r);
    cudaGetSymbolAddress((void**)&acc, g_acc);
    cudaGetSymbolAddress((void**)&vbuf, g_v);
    cudaGetSymbolAddress((void**)&h1,  g_h1);
    cudaGetSymbolAddress((void**)&h1r, g_h1r);
    cudaGetSymbolAddress((void**)&h2,  g_h2);
    cudaGetSymbolAddress((void**)&h2r, g_h2r);
    cudaGetSymbolAddress((void**)&xr,  g_xr);
    cudaGetSymbolAddress((void**)&W1r, g_W1r);
    cudaGetSymbolAddress((void**)&W2r, g_W2r);
    cudaGetSymbolAddress((void**)&W3r, g_W3r);
    cudaGetSymbolAddress((void**)&y2b, g_y2b);
    cudaGetSymbolAddress((void**)&T1b, g_T1b);
    cudaGetSymbolAddress((void**)&h1b, g_h1b);
    cudaGetSymbolAddress((void**)&h2b, g_h2b);

    // graph setup
    k_detect<<<1, 512>>>((const int*)ei);
    k_init<<<ceil_div(NNODES, 256), 256>>>();
    k_degree<<<ceil_div(NEDGES, 256), 256>>>(ei);
    k_node<<<ceil_div(NNODES, 256), 256>>>();
    k_scan<<<1, 1024>>>();
    k_scatter<<<ceil_div(NEDGES, 256), 256>>>(ei);

    // operand prep (tf32 RNA)
    k_round<<<ceil_div(NNODES * 512, 256), 256>>>(x, xr, NNODES * 512);
    k_round<<<ceil_div(3 * 512 * 250, 256), 256>>>(w1, W1r, 3 * 512 * 250);
    k_round<<<ceil_div(3 * 250 * 500, 256), 256>>>(w2, W2r, 3 * 250 * 500);
    k_round<<<ceil_div(3 * 500 * 1000, 256), 256>>>(w3, W3r, 3 * 500 * 1000);

    // ---- layer 1 (commuted): y_p = x@W_p, then SpMMs on 250 feats ----
    {
        dim3 ggrid(ceil_div(250, GBN), ceil_div(NNODES, GBM));
        k_gemm1_tc<<<ggrid, 256, GSMEM>>>(xr, W1r + (size_t)2 * 512 * 250,
                                          acc, y2b, NNODES, 512, 250);     // y2 (+bf16)
        k_gemm1_tc<<<ggrid, 256, GSMEM>>>(xr, W1r,
                                          T1r, nullptr, NNODES, 512, 250); // y0
        k_gemm1_tc<<<ggrid, 256, GSMEM>>>(xr, W1r + (size_t)1 * 512 * 250,
                                          T2r, nullptr, NNODES, 512, 250); // y1
        // v = y1 + 2*Lhat(y2)
        k_l1a<<<NNODES, 125>>>((const uint32_t*)y2b, (const float2*)acc,
                               (const float2*)T2r, (float2*)vbuf, (uint32_t*)T1b);
        // h1 = relu(y0 - y2 + Lhat(v) + b1)
        k_l1b<<<NNODES, 125>>>((const uint32_t*)T1b, (const float2*)vbuf,
                               (const float2*)T1r, (const float2*)acc, b1,
                               (float2*)h1, (float2*)h1r, (uint32_t*)h1b);
    }

    // ---- layer 2: Fin=250 (F2=125, vec2), Fout=500 (unchanged R11) ----
    k_spmm_b2<<<NNODES, 125>>>((const uint32_t*)h1b, (const float2*)h1, nullptr,
                               nullptr, (float2*)T1r, (uint32_t*)T1b, 125, 0);
    k_spmm_b2<<<NNODES, 125>>>((const uint32_t*)T1b, (const float2*)T1r, (const float2*)h1,
                               nullptr, (float2*)T2r, nullptr, 125, 1);
    {
        dim3 ggrid(ceil_div(500, GBN), ceil_div(NNODES, GBM));
        k_gemm3_tc<<<ggrid, 256, GSMEM>>>(h1r, T1r, T2r, W2r, b2, h2, h2r, h2b,
                                          NNODES, 250, 500);
    }

    // ---- layer 3: Fin=500 (F4=125, vec4), Fout=1000 (unchanged R11) ----
    k_spmm_b4<<<NNODES, 125>>>((const uint2*)h2b, (const float4*)h2, nullptr,
                               nullptr, (float4*)T1r, (uint2*)T1b, 125, 0);
    k_spmm_b4<<<NNODES, 125>>>((const uint2*)T1b, (const float4*)T1r, (const float4*)h2,
                               nullptr, (float4*)T2r, nullptr, 125, 1);
    {
        dim3 ggrid(ceil_div(1000, GBN), ceil_div(NNODES, GBM));
        k_gemm3_tc<<<ggrid, 256, GSMEM>>>(h2r, T1r, T2r, W3r, b3, out, nullptr, nullptr,
                                          NNODES, 500, 1000);
    }
}

// round 16
// speedup vs baseline: 1.9454x; 1.0349x over previous
#include <cuda_runtime.h>
#include <cuda_bf16.h>
#include <cstdint>

#define NNODES 50000
#define NEDGES 1600000
#define MAXF   512

// ---------------- device scratch (static, no allocation) ----------------
__device__ int   g_flag;
__device__ int   g_deg[NNODES];
__device__ float g_dinv[NNODES];
__device__ float g_diag[NNODES];
__device__ int   g_rowptr[NNODES + 1];
__device__ int   g_cursor[NNODES];
__device__ int   g_ecol[NEDGES];
__device__ float g_ew[NEDGES];
__device__ float g_T1r[(size_t)NNODES * MAXF];
__device__ float g_T2r[(size_t)NNODES * MAXF];
__device__ float g_acc[(size_t)NNODES * 250];     // layer-1 y2
__device__ float g_v  [(size_t)NNODES * 250];     // layer-1 v
__device__ float g_h1 [(size_t)NNODES * 250];
__device__ float g_h1r[(size_t)NNODES * 250];
__device__ float g_h2 [(size_t)NNODES * 500];
__device__ float g_h2r[(size_t)NNODES * 500];
__device__ float g_xr [(size_t)NNODES * 512];
__device__ float g_W1r[3 * 512 * 250];
__device__ float g_W2r[3 * 250 * 500];
__device__ float g_W3r[3 * 500 * 1000];
// bf16 gather copies
__device__ __nv_bfloat16 g_y2b[(size_t)NNODES * 250];
__device__ __nv_bfloat16 g_T1b[(size_t)NNODES * MAXF];
__device__ __nv_bfloat16 g_h1b[(size_t)NNODES * 250];
__device__ __nv_bfloat16 g_h2b[(size_t)NNODES * 500];

__device__ __forceinline__ float to_tf32(float x) {
    float y;
    asm("cvt.rna.tf32.f32 %0, %1;" : "=f"(y) : "f"(x));
    return y;
}

// ---------------- index width detection (parallel) ----------------
__global__ void k_detect(const int* e32) {
    __shared__ int ok;
    if (threadIdx.x == 0) ok = 1;
    __syncthreads();
    if (e32[2 * threadIdx.x + 1] != 0) ok = 0;   // benign race: only writes 0
    __syncthreads();
    if (threadIdx.x == 0) g_flag = ok;
}

__device__ __forceinline__ int load_idx(const void* e, long long i) {
    if (g_flag) return (int)((const long long*)e)[i];
    return ((const int*)e)[i];
}

// ---------------- graph setup ----------------
__global__ void k_init() {
    int i = blockIdx.x * blockDim.x + threadIdx.x;
    if (i < NNODES) { g_deg[i] = 0; g_cursor[i] = 0; }
}

__global__ void k_degree(const void* e) {
    int i = blockIdx.x * blockDim.x + threadIdx.x;
    if (i < NEDGES) {
        int dst = load_idx(e, (long long)NEDGES + i);
        atomicAdd(&g_deg[dst], 1);
    }
}

__global__ void k_node() {
    int i = blockIdx.x * blockDim.x + threadIdx.x;
    if (i < NNODES) {
        int d = g_deg[i];
        g_dinv[i] = d > 0 ? rsqrtf((float)d) : 0.0f;
        g_diag[i] = d > 0 ? 0.0f : -1.0f;
    }
}

__global__ void k_scan() {
    __shared__ int warp_sums[32];
    int tid  = threadIdx.x;
    int lane = tid & 31;
    int wid  = tid >> 5;
    int carry = 0;
    for (int base = 0; base < NNODES; base += 1024) {
        int i = base + tid;
        int v = (i < NNODES) ? g_deg[i] : 0;
        int x = v;
        #pragma unroll
        for (int o = 1; o < 32; o <<= 1) {
            int y = __shfl_up_sync(0xffffffffu, x, o);
            if (lane >= o) x += y;
        }
        if (lane == 31) warp_sums[wid] = x;
        __syncthreads();
        if (tid < 32) {
            int s = warp_sums[tid];
            #pragma unroll
            for (int o = 1; o < 32; o <<= 1) {
                int y = __shfl_up_sync(0xffffffffu, s, o);
                if (tid >= o) s += y;
            }
            warp_sums[tid] = s;
        }
        __syncthreads();
        int incl = x + (wid > 0 ? warp_sums[wid - 1] : 0);
        if (i < NNODES) g_rowptr[i] = carry + incl - v;
        int total = warp_sums[31];
        __syncthreads();
        carry += total;
    }
    if (tid == 0) g_rowptr[NNODES] = carry;
}

__global__ void k_scatter(const void* e) {
    int i = blockIdx.x * blockDim.x + threadIdx.x;
    if (i < NEDGES) {
        int src = load_idx(e, i);
        int dst = load_idx(e, (long long)NEDGES + i);
        float w = -g_dinv[dst] * g_dinv[src];
        int pos = g_rowptr[dst] + atomicAdd(&g_cursor[dst], 1);
        g_ecol[pos] = src;
        g_ew[pos]   = w;
    }
}

// ---------------- rounding helper ----------------
__global__ void k_round(const float* __restrict__ in, float* __restrict__ dst, int n) {
    int i = blockIdx.x * blockDim.x + threadIdx.x;
    if (i < n) dst[i] = to_tf32(in[i]);
}

// ---------------- bf16-gather SpMM (layers 2/3) ----------
__global__ void k_spmm_b4(const uint2* __restrict__ hb, const float4* __restrict__ hs,
                          const float4* __restrict__ t0,
                          float4* __restrict__ out, float4* __restrict__ out_r,
                          uint2* __restrict__ out_b, int F4, int mode) {
    int node = blockIdx.x;
    int f = threadIdx.x;
    if (f >= F4) return;
    int s = g_rowptr[node];
    int e = g_rowptr[node + 1];
    float4 acc = make_float4(0.f, 0.f, 0.f, 0.f);
    for (int j = s; j < e; ++j) {
        int   src = __ldg(&g_ecol[j]);
        float w   = __ldg(&g_ew[j]);
        uint2 v = __ldg(&hb[(size_t)src * F4 + f]);
        __nv_bfloat162 p0 = *reinterpret_cast<const __nv_bfloat162*>(&v.x);
        __nv_bfloat162 p1 = *reinterpret_cast<const __nv_bfloat162*>(&v.y);
        float2 f0 = __bfloat1622float2(p0);
        float2 f1 = __bfloat1622float2(p1);
        acc.x = fmaf(w, f0.x, acc.x);
        acc.y = fmaf(w, f0.y, acc.y);
        acc.z = fmaf(w, f1.x, acc.z);
        acc.w = fmaf(w, f1.y, acc.w);
    }
    float dw = g_diag[node];
    float4 hv = __ldg(&hs[(size_t)node * F4 + f]);
    acc.x = fmaf(dw, hv.x, acc.x);
    acc.y = fmaf(dw, hv.y, acc.y);
    acc.z = fmaf(dw, hv.z, acc.z);
    acc.w = fmaf(dw, hv.w, acc.w);
    if (mode) {
        float4 t = __ldg(&t0[(size_t)node * F4 + f]);
        acc.x = 2.f * acc.x - t.x;
        acc.y = 2.f * acc.y - t.y;
        acc.z = 2.f * acc.z - t.z;
        acc.w = 2.f * acc.w - t.w;
    }
    size_t idx = (size_t)node * F4 + f;
    if (out) out[idx] = acc;
    if (out_r) out_r[idx] =
        make_float4(to_tf32(acc.x), to_tf32(acc.y), to_tf32(acc.z), to_tf32(acc.w));
    if (out_b) {
        __nv_bfloat162 b0 = __float22bfloat162_rn(make_float2(acc.x, acc.y));
        __nv_bfloat162 b1 = __float22bfloat162_rn(make_float2(acc.z, acc.w));
        uint2 u;
        u.x = *reinterpret_cast<uint32_t*>(&b0);
        u.y = *reinterpret_cast<uint32_t*>(&b1);
        out_b[idx] = u;
    }
}

__global__ void k_spmm_b2(const uint32_t* __restrict__ hb, const float2* __restrict__ hs,
                          const float2* __restrict__ t0,
                          float2* __restrict__ out, float2* __restrict__ out_r,
                          uint32_t* __restrict__ out_b, int F2, int mode) {
    int node = blockIdx.x;
    int f = threadIdx.x;
    if (f >= F2) return;
    int s = g_rowptr[node];
    int e = g_rowptr[node + 1];
    float2 acc = make_float2(0.f, 0.f);
    for (int j = s; j < e; ++j) {
        int   src = __ldg(&g_ecol[j]);
        float w   = __ldg(&g_ew[j]);
        uint32_t v = __ldg(&hb[(size_t)src * F2 + f]);
        float2 fv = __bfloat1622float2(*reinterpret_cast<const __nv_bfloat162*>(&v));
        acc.x = fmaf(w, fv.x, acc.x);
        acc.y = fmaf(w, fv.y, acc.y);
    }
    float dw = g_diag[node];
    float2 hv = __ldg(&hs[(size_t)node * F2 + f]);
    acc.x = fmaf(dw, hv.x, acc.x);
    acc.y = fmaf(dw, hv.y, acc.y);
    if (mode) {
        float2 t = __ldg(&t0[(size_t)node * F2 + f]);
        acc.x = 2.f * acc.x - t.x;
        acc.y = 2.f * acc.y - t.y;
    }
    size_t idx = (size_t)node * F2 + f;
    if (out) out[idx] = acc;
    if (out_r) out_r[idx] = make_float2(to_tf32(acc.x), to_tf32(acc.y));
    if (out_b) {
        __nv_bfloat162 b = __float22bfloat162_rn(acc);
        out_b[idx] = *reinterpret_cast<uint32_t*>(&b);
    }
}

// ---------------- layer-1 commuted SpMMs (250 features, vec2) ----------------
__global__ void k_l1a(const uint32_t* __restrict__ y2b, const float2* __restrict__ y2,
                      const float2* __restrict__ y1,
                      float2* __restrict__ v, uint32_t* __restrict__ vb) {
    int node = blockIdx.x;
    int f = threadIdx.x;
    if (f >= 125) return;
    int s = g_rowptr[node];
    int e = g_rowptr[node + 1];
    float2 acc = make_float2(0.f, 0.f);
    for (int j = s; j < e; ++j) {
        int   src = __ldg(&g_ecol[j]);
        float w   = __ldg(&g_ew[j]);
        uint32_t u = __ldg(&y2b[(size_t)src * 125 + f]);
        float2 fv = __bfloat1622float2(*reinterpret_cast<const __nv_bfloat162*>(&u));
        acc.x = fmaf(w, fv.x, acc.x);
        acc.y = fmaf(w, fv.y, acc.y);
    }
    size_t idx = (size_t)node * 125 + f;
    float dw = g_diag[node];
    float2 s2 = __ldg(&y2[idx]);
    acc.x = fmaf(dw, s2.x, acc.x);
    acc.y = fmaf(dw, s2.y, acc.y);
    float2 a1 = __ldg(&y1[idx]);
    float2 vv = make_float2(a1.x + 2.f * acc.x, a1.y + 2.f * acc.y);
    v[idx] = vv;
    __nv_bfloat162 b = __float22bfloat162_rn(vv);
    vb[idx] = *reinterpret_cast<uint32_t*>(&b);
}

__global__ void k_l1b(const uint32_t* __restrict__ vb, const float2* __restrict__ v,
                      const float2* __restrict__ y0, const float2* __restrict__ y2,
                      const float* __restrict__ bias,
                      float2* __restrict__ h1, float2* __restrict__ h1r,
                      uint32_t* __restrict__ h1b) {
    int node = blockIdx.x;
    int f = threadIdx.x;
    if (f >= 125) return;
    int s = g_rowptr[node];
    int e = g_rowptr[node + 1];
    float2 acc = make_float2(0.f, 0.f);
    for (int j = s; j < e; ++j) {
        int   src = __ldg(&g_ecol[j]);
        float w   = __ldg(&g_ew[j]);
        uint32_t u = __ldg(&vb[(size_t)src * 125 + f]);
        float2 fv = __bfloat1622float2(*reinterpret_cast<const __nv_bfloat162*>(&u));
        acc.x = fmaf(w, fv.x, acc.x);
        acc.y = fmaf(w, fv.y, acc.y);
    }
    size_t idx = (size_t)node * 125 + f;
    float dw = g_diag[node];
    float2 sv = __ldg(&v[idx]);
    acc.x = fmaf(dw, sv.x, acc.x);
    acc.y = fmaf(dw, sv.y, acc.y);
    float2 a0 = __ldg(&y0[idx]);
    float2 a2 = __ldg(&y2[idx]);
    float b0 = bias[2 * f], b1 = bias[2 * f + 1];
    float o0 = a0.x - a2.x + acc.x + b0;
    float o1 = a0.y - a2.y + acc.y + b1;
    o0 = o0 > 0.f ? o0 : 0.f;
    o1 = o1 > 0.f ? o1 : 0.f;
    h1[idx] = make_float2(o0, o1);
    h1r[idx] = make_float2(to_tf32(o0), to_tf32(o1));
    __nv_bfloat162 b = __float22bfloat162_rn(make_float2(o0, o1));
    h1b[idx] = *reinterpret_cast<uint32_t*>(&b);
}

// ---------------- TF32 GEMM core (R11 mainloop, unchanged) -------------------
__device__ __forceinline__ void mma_tf32(float* c, const uint32_t* a, const uint32_t* b) {
    asm volatile(
        "mma.sync.aligned.m16n8k8.row.col.f32.tf32.tf32.f32 "
        "{%0,%1,%2,%3}, {%4,%5,%6,%7}, {%8,%9}, {%0,%1,%2,%3};"
        : "+f"(c[0]), "+f"(c[1]), "+f"(c[2]), "+f"(c[3])
        : "r"(a[0]), "r"(a[1]), "r"(a[2]), "r"(a[3]), "r"(b[0]), "r"(b[1]));
}

__device__ __forceinline__ void cp_async8(uint32_t dst, const void* src, int sz) {
    asm volatile("cp.async.ca.shared.global [%0], [%1], 8, %2;"
                 :: "r"(dst), "l"(src), "r"(sz));
}
__device__ __forceinline__ void cp_commit() { asm volatile("cp.async.commit_group;"); }
template<int N> __device__ __forceinline__ void cp_wait() {
    asm volatile("cp.async.wait_group %0;" :: "n"(N));
}

#define GBM 128
#define GBN 128
#define GBK 16
#define GST 3
#define ASTRIDE 20
#define BSTRIDE 136
#define GSMEM ((GST*GBM*ASTRIDE + GST*GBK*BSTRIDE) * 4)

template<int NMAT>
__device__ __forceinline__ void gemm_mainloop(
    const float* A0, const float* A1, const float* A2, const float* W,
    int M, int K, int Nout, int bm, int bn, float acc[4][4][4])
{
    extern __shared__ float smem[];
    float* As = smem;
    float* Bs = smem + GST * GBM * ASTRIDE;
    uint32_t sA = (uint32_t)__cvta_generic_to_shared(As);
    uint32_t sB = (uint32_t)__cvta_generic_to_shared(Bs);

    int tid  = threadIdx.x;
    int wid  = tid >> 5;
    int lane = tid & 31;
    int g    = lane >> 2;
    int tig  = lane & 3;
    int wm   = wid & 1;
    int wn   = wid >> 1;

    int kt = (K + GBK - 1) / GBK;
    int nt = NMAT * kt;

    auto issue_tile = [&](int t) {
        int pn = t / kt;
        int k0 = (t - pn * kt) * GBK;
        int s  = t % GST;
        const float* A = (pn == 0) ? A0 : ((pn == 1) ? A1 : A2);
        #pragma unroll
        for (int q = 0; q < 4; ++q) {
            int p  = q * 256 + tid;
            int m  = p >> 3;
            int kk = (p & 7) * 2;
            int gm = bm + m, gk = k0 + kk;
            int sz = (gm < M && gk < K) ? 8 : 0;
            const float* src = sz ? (A + (size_t)gm * K + gk) : A;
            uint32_t dst = sA + (uint32_t)(((s * GBM + m) * ASTRIDE + kk) * 4);
            cp_async8(dst, src, sz);
        }
        const float* B = W + (size_t)pn * K * Nout;
        #pragma unroll
        for (int q = 0; q < 4; ++q) {
            int p  = q * 256 + tid;
            int r  = p >> 6;
            int n0 = (p & 63) * 2;
            int gk = k0 + r, gn = bn + n0;
            int sz = (gk < K && gn < Nout) ? 8 : 0;
            const float* src = sz ? (B + (size_t)gk * Nout + gn) : B;
            uint32_t dst = sB + (uint32_t)(((s * GBK + r) * BSTRIDE + n0) * 4);
            cp_async8(dst, src, sz);
        }
    };

    #pragma unroll
    for (int t = 0; t < GST - 1; ++t) {
        issue_tile(t);
        cp_commit();
    }

    for (int t = 0; t < nt; ++t) {
        cp_wait<GST - 2>();
        __syncthreads();

        int tn = t + GST - 1;
        if (tn < nt) issue_tile(tn);
        cp_commit();

        int s = t % GST;
        const float* Ab = As + s * GBM * ASTRIDE;
        const float* Bb = Bs + s * GBK * BSTRIDE;
        #pragma unroll
        for (int ks = 0; ks < GBK; ks += 8) {
            uint32_t af[4][4];
            uint32_t bf[4][2];
            #pragma unroll
            for (int mi = 0; mi < 4; ++mi) {
                int mb = wm * 64 + mi * 16;
                af[mi][0] = __float_as_uint(Ab[(mb + g    ) * ASTRIDE + ks + tig    ]);
                af[mi][1] = __float_as_uint(Ab[(mb + g + 8) * ASTRIDE + ks + tig    ]);
                af[mi][2] = __float_as_uint(Ab[(mb + g    ) * ASTRIDE + ks + tig + 4]);
                af[mi][3] = __float_as_uint(Ab[(mb + g + 8) * ASTRIDE + ks + tig + 4]);
            }
            #pragma unroll
            for (int ni = 0; ni < 4; ++ni) {
                int nb = wn * 32 + ni * 8;
                bf[ni][0] = __float_as_uint(Bb[(ks + tig    ) * BSTRIDE + nb + g]);
                bf[ni][1] = __float_as_uint(Bb[(ks + tig + 4) * BSTRIDE + nb + g]);
            }
            #pragma unroll
            for (int mi = 0; mi < 4; ++mi)
                #pragma unroll
                for (int ni = 0; ni < 4; ++ni)
                    mma_tf32(acc[mi][ni], af[mi], bf[ni]);
        }
        __syncthreads();
    }
}

__global__ __launch_bounds__(256, 2) void k_gemm3_tc(
    const float* __restrict__ A0, const float* __restrict__ A1,
    const float* __restrict__ A2, const float* __restrict__ W,
    const float* __restrict__ bias, float* __restrict__ out,
    float* __restrict__ out_r, __nv_bfloat16* __restrict__ out_b,
    int M, int K, int Nout)
{
    int bm = blockIdx.y * GBM;
    int bn = blockIdx.x * GBN;
    float acc[4][4][4];
    #pragma unroll
    for (int mi = 0; mi < 4; ++mi)
        #pragma unroll
        for (int ni = 0; ni < 4; ++ni)
            #pragma unroll
            for (int r = 0; r < 4; ++r) acc[mi][ni][r] = 0.0f;

    gemm_mainloop<3>(A0, A1, A2, W, M, K, Nout, bm, bn, acc);

    int tid  = threadIdx.x;
    int wid  = tid >> 5;
    int lane = tid & 31;
    int g    = lane >> 2;
    int tig  = lane & 3;
    int wm   = wid & 1;
    int wn   = wid >> 1;

    #pragma unroll
    for (int mi = 0; mi < 4; ++mi) {
        int r0 = bm + wm * 64 + mi * 16 + g;
        int r1 = r0 + 8;
        #pragma unroll
        for (int ni = 0; ni < 4; ++ni) {
            int c0 = bn + wn * 32 + ni * 8 + 2 * tig;
            if (c0 >= Nout) continue;
            float bv0 = bias[c0];
            float bv1 = bias[c0 + 1];
            if (r0 < M) {
                float v0 = acc[mi][ni][0] + bv0; v0 = v0 > 0.f ? v0 : 0.f;
                float v1 = acc[mi][ni][1] + bv1; v1 = v1 > 0.f ? v1 : 0.f;
                size_t o = (size_t)r0 * Nout + c0;
                out[o] = v0; out[o + 1] = v1;
                if (out_r) { out_r[o] = to_tf32(v0); out_r[o + 1] = to_tf32(v1); }
                if (out_b) {
                    __nv_bfloat162 b = __float22bfloat162_rn(make_float2(v0, v1));
                    *reinterpret_cast<uint32_t*>(out_b + o) = *reinterpret_cast<uint32_t*>(&b);
                }
            }
            if (r1 < M) {
                float v0 = acc[mi][ni][2] + bv0; v0 = v0 > 0.f ? v0 : 0.f;
                float v1 = acc[mi][ni][3] + bv1; v1 = v1 > 0.f ? v1 : 0.f;
                size_t o = (size_t)r1 * Nout + c0;
                out[o] = v0; out[o + 1] = v1;
                if (out_r) { out_r[o] = to_tf32(v0); out_r[o + 1] = to_tf32(v1); }
                if (out_b) {
                    __nv_bfloat162 b = __float22bfloat162_rn(make_float2(v0, v1));
                    *reinterpret_cast<uint32_t*>(out_b + o) = *reinterpret_cast<uint32_t*>(&b);
                }
            }
        }
    }
}

__global__ __launch_bounds__(256, 2) void k_gemm1_tc(
    const float* __restrict__ A0, const float* __restrict__ W,
    float* __restrict__ out, __nv_bfloat16* __restrict__ out_b,
    int M, int K, int Nout)
{
    int bm = blockIdx.y * GBM;
    int bn = blockIdx.x * GBN;
    float acc[4][4][4];
    #pragma unroll
    for (int mi = 0; mi < 4; ++mi)
        #pragma unroll
        for (int ni = 0; ni < 4; ++ni)
            #pragma unroll
            for (int r = 0; r < 4; ++r) acc[mi][ni][r] = 0.0f;

    gemm_mainloop<1>(A0, A0, A0, W, M, K, Nout, bm, bn, acc);

    int tid  = threadIdx.x;
    int wid  = tid >> 5;
    int lane = tid & 31;
    int g    = lane >> 2;
    int tig  = lane & 3;
    int wm   = wid & 1;
    int wn   = wid >> 1;

    #pragma unroll
    for (int mi = 0; mi < 4; ++mi) {
        int r0 = bm + wm * 64 + mi * 16 + g;
        int r1 = r0 + 8;
        #pragma unroll
        for (int ni = 0; ni < 4; ++ni) {
            int c0 = bn + wn * 32 + ni * 8 + 2 * tig;
            if (c0 >= Nout) continue;
            if (r0 < M) {
                size_t o = (size_t)r0 * Nout + c0;
                float v0 = acc[mi][ni][0], v1 = acc[mi][ni][1];
                out[o] = v0; out[o + 1] = v1;
                if (out_b) {
                    __nv_bfloat162 b = __float22bfloat162_rn(make_float2(v0, v1));
                    *reinterpret_cast<uint32_t*>(out_b + o) = *reinterpret_cast<uint32_t*>(&b);
                }
            }
            if (r1 < M) {
                size_t o = (size_t)r1 * Nout + c0;
                float v0 = acc[mi][ni][2], v1 = acc[mi][ni][3];
                out[o] = v0; out[o + 1] = v1;
                if (out_b) {
                    __nv_bfloat162 b = __float22bfloat162_rn(make_float2(v0, v1));
                    *reinterpret_cast<uint32_t*>(out_b + o) = *reinterpret_cast<uint32_t*>(&b);
                }
            }
        }
    }
}

// ---------------- host side ----------------
static inline int ceil_div(int a, int b) { return (a + b - 1) / b; }

extern "C" void kernel_launch(void* const* d_in, const int* in_sizes, int n_in,
                              void* d_out, int out_size) {
    const float* x  = (const float*)d_in[0];
    const void*  ei = d_in[1];
    const float* w1 = (const float*)d_in[2];
    const float* b1 = (const float*)d_in[3];
    const float* w2 = (const float*)d_in[4];
    const float* b2 = (const float*)d_in[5];
    const float* w3 = (const float*)d_in[6];
    const float* b3 = (const float*)d_in[7];
    float* out = (float*)d_out;

    // one-time host-side init (first call is the uncaptured correctness run)
    static cudaStream_t s2 = nullptr, s3 = nullptr;
    static cudaEvent_t e0, e1, e2, e3;
    if (!s2) {
        cudaFuncSetAttribute(k_gemm3_tc, cudaFuncAttributeMaxDynamicSharedMemorySize, GSMEM);
        cudaFuncSetAttribute(k_gemm1_tc, cudaFuncAttributeMaxDynamicSharedMemorySize, GSMEM);
        cudaStreamCreateWithFlags(&s2, cudaStreamNonBlocking);
        cudaStreamCreateWithFlags(&s3, cudaStreamNonBlocking);
        cudaEventCreateWithFlags(&e0, cudaEventDisableTiming);
        cudaEventCreateWithFlags(&e1, cudaEventDisableTiming);
        cudaEventCreateWithFlags(&e2, cudaEventDisableTiming);
        cudaEventCreateWithFlags(&e3, cudaEventDisableTiming);
    }

    float *T1r, *T2r, *acc, *vbuf, *h1, *h1r, *h2, *h2r, *xr, *W1r, *W2r, *W3r;
    __nv_bfloat16 *y2b, *T1b, *h1b, *h2b;
    cudaGetSymbolAddress((void**)&T1r, g_T1r);
    cudaGetSymbolAddress((void**)&T2r, g_T2r);
    cudaGetSymbolAddress((void**)&acc, g_acc);
    cudaGetSymbolAddress((void**)&vbuf, g_v);
    cudaGetSymbolAddress((void**)&h1,  g_h1);
    cudaGetSymbolAddress((void**)&h1r, g_h1r);
    cudaGetSymbolAddress((void**)&h2,  g_h2);
    cudaGetSymbolAddress((void**)&h2r, g_h2r);
    cudaGetSymbolAddress((void**)&xr,  g_xr);
    cudaGetSymbolAddress((void**)&W1r, g_W1r);
    cudaGetSymbolAddress((void**)&W2r, g_W2r);
    cudaGetSymbolAddress((void**)&W3r, g_W3r);
    cudaGetSymbolAddress((void**)&y2b, g_y2b);
    cudaGetSymbolAddress((void**)&T1b, g_T1b);
    cudaGetSymbolAddress((void**)&h1b, g_h1b);
    cudaGetSymbolAddress((void**)&h2b, g_h2b);

    cudaStream_t st0 = 0;   // capture stream (legacy default)

    // ---- fork s2: graph setup + W2/W3 rounding (independent of GEMM path) ----
    cudaEventRecord(e0, st0);
    cudaStreamWaitEvent(s2, e0, 0);
    k_detect<<<1, 512, 0, s2>>>((const int*)ei);
    k_init<<<ceil_div(NNODES, 256), 256, 0, s2>>>();
    k_degree<<<ceil_div(NEDGES, 256), 256, 0, s2>>>(ei);
    k_node<<<ceil_div(NNODES, 256), 256, 0, s2>>>();
    k_scan<<<1, 1024, 0, s2>>>();
    k_scatter<<<ceil_div(NEDGES, 256), 256, 0, s2>>>(ei);
    k_round<<<ceil_div(3 * 250 * 500, 256), 256, 0, s2>>>(w2, W2r, 3 * 250 * 500);
    k_round<<<ceil_div(3 * 500 * 1000, 256), 256, 0, s2>>>(w3, W3r, 3 * 500 * 1000);
    cudaEventRecord(e1, s2);

    // ---- st0: x/W1 rounding, then layer-1 GEMMs (graph-independent) ----
    k_round<<<ceil_div(NNODES * 512, 256), 256, 0, st0>>>(x, xr, NNODES * 512);
    k_round<<<ceil_div(3 * 512 * 250, 256), 256, 0, st0>>>(w1, W1r, 3 * 512 * 250);
    cudaEventRecord(e2, st0);

    // ---- fork s3: gemm1(y0) — not needed until l1b ----
    cudaStreamWaitEvent(s3, e2, 0);
    {
        dim3 ggrid(ceil_div(250, GBN), ceil_div(NNODES, GBM));
        k_gemm1_tc<<<ggrid, 256, GSMEM, s3>>>(xr, W1r,
                                              T1r, nullptr, NNODES, 512, 250); // y0
    }
    cudaEventRecord(e3, s3);

    // ---- st0: y2, y1, then commuted SpMMs ----
    {
        dim3 ggrid(ceil_div(250, GBN), ceil_div(NNODES, GBM));
        k_gemm1_tc<<<ggrid, 256, GSMEM, st0>>>(xr, W1r + (size_t)2 * 512 * 250,
                                               acc, y2b, NNODES, 512, 250);    // y2
        k_gemm1_tc<<<ggrid, 256, GSMEM, st0>>>(xr, W1r + (size_t)1 * 512 * 250,
                                               T2r, nullptr, NNODES, 512, 250); // y1
    }
    cudaStreamWaitEvent(st0, e1, 0);    // join s2: graph ready
    // v = y1 + 2*Lhat(y2)   (overlaps with gemm1(y0) on s3)
    k_l1a<<<NNODES, 125, 0, st0>>>((const uint32_t*)y2b, (const float2*)acc,
                                   (const float2*)T2r, (float2*)vbuf, (uint32_t*)T1b);
    cudaStreamWaitEvent(st0, e3, 0);    // join s3: y0 ready
    // h1 = relu(y0 - y2 + Lhat(v) + b1)
    k_l1b<<<NNODES, 125, 0, st0>>>((const uint32_t*)T1b, (const float2*)vbuf,
                                   (const float2*)T1r, (const float2*)acc, b1,
                                   (float2*)h1, (float2*)h1r, (uint32_t*)h1b);

    // ---- layer 2: Fin=250 (vec2), Fout=500 ----
    k_spmm_b2<<<NNODES, 125, 0, st0>>>((const uint32_t*)h1b, (const float2*)h1, nullptr,
                                       nullptr, (float2*)T1r, (uint32_t*)T1b, 125, 0);
    k_spmm_b2<<<NNODES, 125, 0, st0>>>((const uint32_t*)T1b, (const float2*)T1r,
                                       (const float2*)h1,
                                       nullptr, (float2*)T2r, nullptr, 125, 1);
    {
        dim3 ggrid(ceil_div(500, GBN), ceil_div(NNODES, GBM));
        k_gemm3_tc<<<ggrid, 256, GSMEM, st0>>>(h1r, T1r, T2r, W2r, b2, h2, h2r, h2b,
                                               NNODES, 250, 500);
    }

    // ---- layer 3: Fin=500 (vec4), Fout=1000 ----
    k_spmm_b4<<<NNODES, 125, 0, st0>>>((const uint2*)h2b, (const float4*)h2, nullptr,
                                       nullptr, (float4*)T1r, (uint2*)T1b, 125, 0);
    k_spmm_b4<<<NNODES, 125, 0, st0>>>((const uint2*)T1b, (const float4*)T1r,
                                       (const float4*)h2,
                                       nullptr, (float4*)T2r, nullptr, 125, 1);
    {
        dim3 ggrid(ceil_div(1000, GBN), ceil_div(NNODES, GBM));
        k_gemm3_tc<<<ggrid, 256, GSMEM, st0>>>(h2r, T1r, T2r, W3r, b3, out,
                                               nullptr, nullptr, NNODES, 500, 1000);
    }
}